// round 3
// baseline (speedup 1.0000x reference)
#include <cuda_runtime.h>

// SSIM on GB300: separable 11x11 gaussian, fused single kernel.
//   - full-width row strips (1024 cols), 512 threads x 2 cols each (f32x2 packed)
//   - vertical conv of {x, y, x^2, y^2, xy} via register ring of 11 input rows
//   - two rows per step; results staged row-pair-interleaved in DOUBLE-BUFFERED SMEM
//     -> ONE __syncthreads per row-pair instead of two
//   - next row-pair's global loads prefetched before the horizontal pass
//   - horizontal conv reads 7 conflict-free LDS.128 per quantity per thread
//   - SSIM epilogue in f32x2, block reduce, atomicAdd of partial mean

#define IW 1024
#define IH 1024
#define NIMG 16
#define OUT_H 16          // output rows per block
#define NTHREADS 512
#define KS 11
#define PADF 2080         // floats per quantity per buffer (col -8..1031, x2 rows)
#define NPIX_INV (1.0f / 16777216.0f)
#define SMEM_BYTES (2 * 5 * PADF * 4)   // 83200 B (double buffered)

typedef unsigned long long u64;

__device__ __forceinline__ u64 f2pack(float lo, float hi) {
    u64 r; asm("mov.b64 %0,{%1,%2};" : "=l"(r) : "f"(lo), "f"(hi)); return r;
}
__device__ __forceinline__ void f2unpack(u64 v, float &lo, float &hi) {
    asm("mov.b64 {%0,%1},%2;" : "=f"(lo), "=f"(hi) : "l"(v));
}
__device__ __forceinline__ u64 f2mul(u64 a, u64 b) {
    u64 r; asm("mul.rn.f32x2 %0,%1,%2;" : "=l"(r) : "l"(a), "l"(b)); return r;
}
__device__ __forceinline__ u64 f2add(u64 a, u64 b) {
    u64 r; asm("add.rn.f32x2 %0,%1,%2;" : "=l"(r) : "l"(a), "l"(b)); return r;
}
__device__ __forceinline__ u64 f2fma(u64 a, u64 b, u64 c) {
    u64 r; asm("fma.rn.f32x2 %0,%1,%2,%3;" : "=l"(r) : "l"(a), "l"(b), "l"(c)); return r;
}

__global__ void __launch_bounds__(NTHREADS, 1)
ssim_kernel(const float* __restrict__ img1, const float* __restrict__ img2,
            const float* __restrict__ kern, float* __restrict__ out)
{
    extern __shared__ __align__(16) float dyn[];   // [2][5][PADF]
    __shared__ float sG[KS];
    __shared__ float sred[NTHREADS / 32];

    const int t = threadIdx.x;
    const int r0 = blockIdx.x * OUT_H;
    const int img = blockIdx.y;

    // 1D gaussian weights = row sums of the (normalized) 2D kernel
    if (t < KS) {
        float s = 0.f;
        #pragma unroll
        for (int j = 0; j < KS; j++) s += kern[t * KS + j];
        sG[t] = s;
    }
    // zero horizontal pads of BOTH buffers: float idx [0,16) and [2064,2080)
    for (int i = t; i < 2 * 5 * 32; i += NTHREADS) {
        int plane = i / 32, j = i % 32;
        int idx = (j < 16) ? j : (2064 + j - 16);
        dyn[plane * PADF + idx] = 0.f;
    }
    __syncthreads();

    // packed symmetric weights (g[k] == g[10-k])
    u64 G2[6];
    #pragma unroll
    for (int k = 0; k < 6; k++) { float g = sG[k]; G2[k] = f2pack(g, g); }

    const u64 C1p  = f2pack(1e-4f, 1e-4f);
    const u64 C2p  = f2pack(9e-4f, 9e-4f);
    const u64 TWO2 = f2pack(2.f, 2.f);
    const u64 NEG1 = f2pack(-1.f, -1.f);

    const u64* __restrict__ p1 = (const u64*)img1 + (size_t)img * (IH * (IW / 2));
    const u64* __restrict__ p2 = (const u64*)img2 + (size_t)img * (IH * (IW / 2));

    // register ring: 11 rows of packed (x pair, y pair) for this thread's 2 cols
    u64 RX[KS], RY[KS];
    #pragma unroll
    for (int s = 0; s < 10; s++) {
        int r = r0 - 5 + s;
        bool v = (r >= 0) & (r < IH);
        RX[s] = v ? p1[(size_t)r * (IW / 2) + t] : 0ull;
        RY[s] = v ? p2[(size_t)r * (IW / 2) + t] : 0ull;
    }
    RX[10] = 0ull; RY[10] = 0ull;

    // prefetch the first new row pair (rows r0+5, r0+6)
    u64 pfx0, pfy0, pfx1, pfy1;
    {
        int r = r0 + 5; bool v = r < IH;
        pfx0 = v ? p1[(size_t)r * (IW / 2) + t] : 0ull;
        pfy0 = v ? p2[(size_t)r * (IW / 2) + t] : 0ull;
    }
    {
        int r = r0 + 6; bool v = r < IH;
        pfx1 = v ? p1[(size_t)r * (IW / 2) + t] : 0ull;
        pfy1 = v ? p2[(size_t)r * (IW / 2) + t] : 0ull;
    }

    float accS = 0.f;

    #pragma unroll
    for (int p = 0; p < OUT_H / 2; p++) {
        float* __restrict__ bp = dyn + (p & 1) * (5 * PADF);

        // ---- pass 1: vertical conv, rows A = r0+2p and B = r0+2p+1 ----
        RX[(10 + 2 * p) % KS] = pfx0;
        RY[(10 + 2 * p) % KS] = pfy0;
        u64 axA = 0, ayA = 0, axxA = 0, ayyA = 0, axyA = 0;
        #pragma unroll
        for (int k = 0; k < KS; k++) {
            const int s = (2 * p + k) % KS;
            const u64 g = G2[(k < 6) ? k : (10 - k)];
            u64 tx = f2mul(g, RX[s]);
            axA  = f2add(axA, tx);
            axxA = f2fma(tx, RX[s], axxA);
            u64 ty = f2mul(g, RY[s]);
            ayA  = f2add(ayA, ty);
            ayyA = f2fma(ty, RY[s], ayyA);
            axyA = f2fma(ty, RX[s], axyA);
        }
        RX[(2 * p) % KS] = pfx1;
        RY[(2 * p) % KS] = pfy1;
        u64 axB = 0, ayB = 0, axxB = 0, ayyB = 0, axyB = 0;
        #pragma unroll
        for (int k = 0; k < KS; k++) {
            const int s = (2 * p + 1 + k) % KS;
            const u64 g = G2[(k < 6) ? k : (10 - k)];
            u64 tx = f2mul(g, RX[s]);
            axB  = f2add(axB, tx);
            axxB = f2fma(tx, RX[s], axxB);
            u64 ty = f2mul(g, RY[s]);
            ayB  = f2add(ayB, ty);
            ayyB = f2fma(ty, RY[s], ayyB);
            axyB = f2fma(ty, RX[s], axyB);
        }

        // ---- prefetch next row pair; latency covered by horizontal pass ----
        if (p < OUT_H / 2 - 1) {
            {
                int r = r0 + 7 + 2 * p; bool v = r < IH;
                pfx0 = v ? p1[(size_t)r * (IW / 2) + t] : 0ull;
                pfy0 = v ? p2[(size_t)r * (IW / 2) + t] : 0ull;
            }
            {
                int r = r0 + 8 + 2 * p; bool v = r < IH;
                pfx1 = v ? p1[(size_t)r * (IW / 2) + t] : 0ull;
                pfy1 = v ? p2[(size_t)r * (IW / 2) + t] : 0ull;
            }
        }

        // store row-pair interleaved: col c -> floats {2c+16 (rowA), 2c+17 (rowB)}
        // this thread's 2 cols (2t, 2t+1) = one contiguous, conflict-free STS.128.
        // Double buffer: readers of this buffer finished before LAST iteration's
        // __syncthreads, so no barrier needed before the stores.
        {
            const int base = 16 + 4 * t;
            float alo, ahi, blo, bhi;
            f2unpack(axA,  alo, ahi); f2unpack(axB,  blo, bhi);
            *(float4*)&bp[0 * PADF + base] = make_float4(alo, blo, ahi, bhi);
            f2unpack(ayA,  alo, ahi); f2unpack(ayB,  blo, bhi);
            *(float4*)&bp[1 * PADF + base] = make_float4(alo, blo, ahi, bhi);
            f2unpack(axxA, alo, ahi); f2unpack(axxB, blo, bhi);
            *(float4*)&bp[2 * PADF + base] = make_float4(alo, blo, ahi, bhi);
            f2unpack(ayyA, alo, ahi); f2unpack(ayyB, blo, bhi);
            *(float4*)&bp[3 * PADF + base] = make_float4(alo, blo, ahi, bhi);
            f2unpack(axyA, alo, ahi); f2unpack(axyB, blo, bhi);
            *(float4*)&bp[4 * PADF + base] = make_float4(alo, blo, ahi, bhi);
        }
        __syncthreads();   // the only barrier per row-pair

        // ---- pass 2: horizontal conv + SSIM, output cols 2t and 2t+1 ----
        u64 acc0[5], acc1[5];
        #pragma unroll
        for (int q = 0; q < 5; q++) {
            u64 Hh[14];
            const float* qp = &bp[q * PADF + 4 + 4 * t];
            #pragma unroll
            for (int j = 0; j < 7; j++) {
                ulonglong2 hv = *(const ulonglong2*)(qp + 4 * j);
                Hh[2 * j]     = hv.x;
                Hh[2 * j + 1] = hv.y;
            }
            u64 a0 = 0, a1 = 0;
            #pragma unroll
            for (int k = 0; k < KS; k++) {
                const u64 g = G2[(k < 6) ? k : (10 - k)];
                a0 = f2fma(g, Hh[k + 1], a0);   // col 2t,   tap col 2t-5+k
                a1 = f2fma(g, Hh[k + 2], a1);   // col 2t+1, tap col 2t-4+k
            }
            acc0[q] = a0; acc1[q] = a1;
        }

        #pragma unroll
        for (int c = 0; c < 2; c++) {
            u64 mx  = c ? acc1[0] : acc0[0];
            u64 my  = c ? acc1[1] : acc0[1];
            u64 exx = c ? acc1[2] : acc0[2];
            u64 eyy = c ? acc1[3] : acc0[3];
            u64 exy = c ? acc1[4] : acc0[4];

            u64 a    = f2mul(mx, my);
            u64 num1 = f2fma(a, TWO2, C1p);        // 2*mu_x*mu_y + C1
            u64 sxy  = f2fma(a, NEG1, exy);        // E[xy] - mu_x*mu_y
            u64 num2 = f2fma(sxy, TWO2, C2p);      // 2*sigma_xy + C2
            u64 b    = f2mul(mx, mx);
            u64 cc   = f2mul(my, my);
            u64 den1 = f2add(f2add(b, cc), C1p);   // mu_x^2 + mu_y^2 + C1
            u64 vx   = f2fma(b, NEG1, exx);        // sigma_x^2
            u64 vy   = f2fma(cc, NEG1, eyy);       // sigma_y^2
            u64 den2 = f2add(f2add(vx, vy), C2p);
            u64 num  = f2mul(num1, num2);
            u64 den  = f2mul(den1, den2);
            float n0, n1, d0, d1;
            f2unpack(num, n0, n1);
            f2unpack(den, d0, d1);
            accS += __fdividef(n0, d0) + __fdividef(n1, d1);
        }
    }

    // ---- block reduce + global accumulate ----
    #pragma unroll
    for (int o = 16; o > 0; o >>= 1)
        accS += __shfl_down_sync(0xffffffffu, accS, o);
    if ((t & 31) == 0) sred[t >> 5] = accS;
    __syncthreads();
    if (t == 0) {
        float s = 0.f;
        #pragma unroll
        for (int w = 0; w < NTHREADS / 32; w++) s += sred[w];
        atomicAdd(out, s * NPIX_INV);
    }
}

__global__ void zero_kernel(float* o, int n) {
    int i = blockIdx.x * blockDim.x + threadIdx.x;
    if (i < n) o[i] = 0.f;
}

extern "C" void kernel_launch(void* const* d_in, const int* in_sizes, int n_in,
                              void* d_out, int out_size)
{
    const float* img1 = (const float*)d_in[0];
    const float* img2 = (const float*)d_in[1];
    const float* kern = (const float*)d_in[2];
    float* out = (float*)d_out;

    // dynamic SMEM opt-in (83.2 KB > default 48 KB). Non-stream API: safe under
    // graph capture; called every launch (deterministic, no static guards).
    cudaFuncSetAttribute(ssim_kernel,
                         cudaFuncAttributeMaxDynamicSharedMemorySize, SMEM_BYTES);

    zero_kernel<<<(out_size + 127) / 128, 128>>>(out, out_size);

    dim3 grid(IH / OUT_H, NIMG);   // 64 strips x 16 images = 1024 blocks
    ssim_kernel<<<grid, NTHREADS, SMEM_BYTES>>>(img1, img2, kern, out);
}

// round 8
// speedup vs baseline: 1.0670x; 1.0670x over previous
#include <cuda_runtime.h>

// SSIM on GB300: separable 11x11 gaussian, fused single kernel.
//   - full-width row strips (1024 cols), 512 threads x 2 cols each (f32x2 packed)
//   - vertical conv of {x, y, x^2, y^2, xy} in fp32 via register ring of 11 rows
//   - two rows per step; vertical results staged in SMEM as HALF2 (rowA,rowB per col)
//     -> halves shared-memory crossbar traffic (the R2-measured top pipe, 62.8%)
//   - horizontal conv: 7 uniformly-aligned LDS.64 per quantity, F16->F32 convert,
//     f32x2 accumulate (rows packed), fp32 SSIM epilogue
//   - block reduce, atomicAdd of partial mean

#define IW 1024
#define IH 1024
#define NIMG 16
#define OUT_H 16          // output rows per block
#define NTHREADS 512
#define KS 11
#define HPAD 1048         // half2 slots per quantity: col c -> idx c+8, cols -8..1039
#define NPIX_INV (1.0f / 16777216.0f)

typedef unsigned long long u64;
typedef unsigned int u32;

__device__ __forceinline__ u64 f2pack(float lo, float hi) {
    u64 r; asm("mov.b64 %0,{%1,%2};" : "=l"(r) : "f"(lo), "f"(hi)); return r;
}
__device__ __forceinline__ void f2unpack(u64 v, float &lo, float &hi) {
    asm("mov.b64 {%0,%1},%2;" : "=f"(lo), "=f"(hi) : "l"(v));
}
__device__ __forceinline__ u64 f2mul(u64 a, u64 b) {
    u64 r; asm("mul.rn.f32x2 %0,%1,%2;" : "=l"(r) : "l"(a), "l"(b)); return r;
}
__device__ __forceinline__ u64 f2add(u64 a, u64 b) {
    u64 r; asm("add.rn.f32x2 %0,%1,%2;" : "=l"(r) : "l"(a), "l"(b)); return r;
}
__device__ __forceinline__ u64 f2fma(u64 a, u64 b, u64 c) {
    u64 r; asm("fma.rn.f32x2 %0,%1,%2,%3;" : "=l"(r) : "l"(a), "l"(b), "l"(c)); return r;
}
// pack two f32 into f16x2: result = {lo=cvt(lo_f), hi=cvt(hi_f)}
__device__ __forceinline__ u32 h2pack(float lo_f, float hi_f) {
    u32 r; asm("cvt.rn.f16x2.f32 %0, %1, %2;" : "=r"(r) : "f"(hi_f), "f"(lo_f)); return r;
}
// unpack f16x2 -> packed f32x2 (lo half -> lo float)
__device__ __forceinline__ u64 h2tof2(u32 h) {
    float lo, hi;
    asm("{.reg .b16 a,b; mov.b32 {a,b}, %2;\n\t"
        "cvt.f32.f16 %0, a; cvt.f32.f16 %1, b;}"
        : "=f"(lo), "=f"(hi) : "r"(h));
    return f2pack(lo, hi);
}

__global__ void __launch_bounds__(NTHREADS, 1)
ssim_kernel(const float* __restrict__ img1, const float* __restrict__ img2,
            const float* __restrict__ kern, float* __restrict__ out)
{
    __shared__ __align__(16) u32 hbuf[5][HPAD];   // 20960 B (half2 per column)
    __shared__ float sG[KS];
    __shared__ float sred[NTHREADS / 32];

    const int t = threadIdx.x;
    const int r0 = blockIdx.x * OUT_H;
    const int img = blockIdx.y;

    // 1D gaussian weights = row sums of the (normalized) 2D kernel
    if (t < KS) {
        float s = 0.f;
        #pragma unroll
        for (int j = 0; j < KS; j++) s += kern[t * KS + j];
        sG[t] = s;
    }
    // zero border pads: idx [0,8) and [1032,1048) of each quantity (cols outside image)
    for (int i = t; i < 5 * 24; i += NTHREADS) {
        int q = i / 24, j = i % 24;
        int idx = (j < 8) ? j : (1032 + j - 8);
        hbuf[q][idx] = 0u;
    }
    __syncthreads();

    // packed symmetric weights (g[k] == g[10-k])
    u64 G2[6];
    #pragma unroll
    for (int k = 0; k < 6; k++) { float g = sG[k]; G2[k] = f2pack(g, g); }

    const u64 C1p  = f2pack(1e-4f, 1e-4f);
    const u64 C2p  = f2pack(9e-4f, 9e-4f);
    const u64 TWO2 = f2pack(2.f, 2.f);
    const u64 NEG1 = f2pack(-1.f, -1.f);

    const u64* __restrict__ p1 = (const u64*)img1 + (size_t)img * (IH * (IW / 2));
    const u64* __restrict__ p2 = (const u64*)img2 + (size_t)img * (IH * (IW / 2));

    // register ring: 11 rows of packed (x pair, y pair) for this thread's 2 cols
    u64 RX[KS], RY[KS];
    #pragma unroll
    for (int s = 0; s < 10; s++) {
        int r = r0 - 5 + s;
        bool v = (r >= 0) & (r < IH);
        RX[s] = v ? p1[(size_t)r * (IW / 2) + t] : 0ull;
        RY[s] = v ? p2[(size_t)r * (IW / 2) + t] : 0ull;
    }
    RX[10] = 0ull; RY[10] = 0ull;

    // prefetch first new row pair (rows r0+5, r0+6)
    u64 pfx0, pfy0, pfx1, pfy1;
    { int r = r0 + 5; bool v = r < IH;
      pfx0 = v ? p1[(size_t)r * (IW / 2) + t] : 0ull;
      pfy0 = v ? p2[(size_t)r * (IW / 2) + t] : 0ull; }
    { int r = r0 + 6; bool v = r < IH;
      pfx1 = v ? p1[(size_t)r * (IW / 2) + t] : 0ull;
      pfy1 = v ? p2[(size_t)r * (IW / 2) + t] : 0ull; }

    float accS = 0.f;

    #pragma unroll
    for (int p = 0; p < OUT_H / 2; p++) {
        // ---- pass 1: vertical conv (fp32), rows A = r0+2p and B = r0+2p+1 ----
        RX[(10 + 2 * p) % KS] = pfx0;
        RY[(10 + 2 * p) % KS] = pfy0;
        u64 axA = 0, ayA = 0, axxA = 0, ayyA = 0, axyA = 0;
        #pragma unroll
        for (int k = 0; k < KS; k++) {
            const int s = (2 * p + k) % KS;
            const u64 g = G2[(k < 6) ? k : (10 - k)];
            u64 tx = f2mul(g, RX[s]);
            axA  = f2add(axA, tx);
            axxA = f2fma(tx, RX[s], axxA);
            u64 ty = f2mul(g, RY[s]);
            ayA  = f2add(ayA, ty);
            ayyA = f2fma(ty, RY[s], ayyA);
            axyA = f2fma(ty, RX[s], axyA);
        }
        RX[(2 * p) % KS] = pfx1;
        RY[(2 * p) % KS] = pfy1;
        u64 axB = 0, ayB = 0, axxB = 0, ayyB = 0, axyB = 0;
        #pragma unroll
        for (int k = 0; k < KS; k++) {
            const int s = (2 * p + 1 + k) % KS;
            const u64 g = G2[(k < 6) ? k : (10 - k)];
            u64 tx = f2mul(g, RX[s]);
            axB  = f2add(axB, tx);
            axxB = f2fma(tx, RX[s], axxB);
            u64 ty = f2mul(g, RY[s]);
            ayB  = f2add(ayB, ty);
            ayyB = f2fma(ty, RY[s], ayyB);
            axyB = f2fma(ty, RX[s], axyB);
        }

        // prefetch next row pair; latency covered by horizontal pass
        if (p < OUT_H / 2 - 1) {
            { int r = r0 + 7 + 2 * p; bool v = r < IH;
              pfx0 = v ? p1[(size_t)r * (IW / 2) + t] : 0ull;
              pfy0 = v ? p2[(size_t)r * (IW / 2) + t] : 0ull; }
            { int r = r0 + 8 + 2 * p; bool v = r < IH;
              pfx1 = v ? p1[(size_t)r * (IW / 2) + t] : 0ull;
              pfy1 = v ? p2[(size_t)r * (IW / 2) + t] : 0ull; }
        }

        __syncthreads();   // previous iteration's readers done

        // ---- stage as half2: col 2t -> {rowA,rowB}, col 2t+1 -> {rowA,rowB} ----
        {
            float alo, ahi, blo, bhi;
            u32 h0, h1;
            f2unpack(axA,  alo, ahi); f2unpack(axB,  blo, bhi);
            h0 = h2pack(alo, blo); h1 = h2pack(ahi, bhi);
            *(uint2*)&hbuf[0][2 * t + 8] = make_uint2(h0, h1);
            f2unpack(ayA,  alo, ahi); f2unpack(ayB,  blo, bhi);
            h0 = h2pack(alo, blo); h1 = h2pack(ahi, bhi);
            *(uint2*)&hbuf[1][2 * t + 8] = make_uint2(h0, h1);
            f2unpack(axxA, alo, ahi); f2unpack(axxB, blo, bhi);
            h0 = h2pack(alo, blo); h1 = h2pack(ahi, bhi);
            *(uint2*)&hbuf[2][2 * t + 8] = make_uint2(h0, h1);
            f2unpack(ayyA, alo, ahi); f2unpack(ayyB, blo, bhi);
            h0 = h2pack(alo, blo); h1 = h2pack(ahi, bhi);
            *(uint2*)&hbuf[3][2 * t + 8] = make_uint2(h0, h1);
            f2unpack(axyA, alo, ahi); f2unpack(axyB, blo, bhi);
            h0 = h2pack(alo, blo); h1 = h2pack(ahi, bhi);
            *(uint2*)&hbuf[4][2 * t + 8] = make_uint2(h0, h1);
        }
        __syncthreads();

        // ---- pass 2: horizontal conv + SSIM, output cols 2t and 2t+1 (rows packed) ----
        u64 acc0[5], acc1[5];
        #pragma unroll
        for (int q = 0; q < 5; q++) {
            // load 14 half2 cols: idx 2t+2 .. 2t+15 (8B-aligned always)
            u32 U[14];
            const uint2* up = (const uint2*)&hbuf[q][2 * t + 2];
            #pragma unroll
            for (int j = 0; j < 7; j++) {
                uint2 v = up[j];
                U[2 * j] = v.x; U[2 * j + 1] = v.y;
            }
            // convert taps once: Hf[i] = f32x2(rowA,rowB) of col 2t-6+i, i=1..13 used
            u64 Hf[14];
            #pragma unroll
            for (int i = 1; i < 14; i++) Hf[i] = h2tof2(U[i]);
            u64 a0 = 0, a1 = 0;
            #pragma unroll
            for (int k = 0; k < KS; k++) {
                const u64 g = G2[(k < 6) ? k : (10 - k)];
                a0 = f2fma(g, Hf[k + 1], a0);   // col 2t,   tap col 2t-5+k
                a1 = f2fma(g, Hf[k + 2], a1);   // col 2t+1, tap col 2t-4+k
            }
            acc0[q] = a0; acc1[q] = a1;
        }

        #pragma unroll
        for (int c = 0; c < 2; c++) {
            u64 mx  = c ? acc1[0] : acc0[0];
            u64 my  = c ? acc1[1] : acc0[1];
            u64 exx = c ? acc1[2] : acc0[2];
            u64 eyy = c ? acc1[3] : acc0[3];
            u64 exy = c ? acc1[4] : acc0[4];

            u64 a    = f2mul(mx, my);
            u64 num1 = f2fma(a, TWO2, C1p);        // 2*mu_x*mu_y + C1
            u64 sxy  = f2fma(a, NEG1, exy);        // E[xy] - mu_x*mu_y
            u64 num2 = f2fma(sxy, TWO2, C2p);      // 2*sigma_xy + C2
            u64 b    = f2mul(mx, mx);
            u64 cc   = f2mul(my, my);
            u64 den1 = f2add(f2add(b, cc), C1p);   // mu_x^2 + mu_y^2 + C1
            u64 vx   = f2fma(b, NEG1, exx);        // sigma_x^2
            u64 vy   = f2fma(cc, NEG1, eyy);       // sigma_y^2
            u64 den2 = f2add(f2add(vx, vy), C2p);
            u64 num  = f2mul(num1, num2);
            u64 den  = f2mul(den1, den2);
            float n0, n1, d0, d1;
            f2unpack(num, n0, n1);
            f2unpack(den, d0, d1);
            accS += __fdividef(n0, d0) + __fdividef(n1, d1);
        }
    }

    // ---- block reduce + global accumulate ----
    #pragma unroll
    for (int o = 16; o > 0; o >>= 1)
        accS += __shfl_down_sync(0xffffffffu, accS, o);
    if ((t & 31) == 0) sred[t >> 5] = accS;
    __syncthreads();
    if (t == 0) {
        float s = 0.f;
        #pragma unroll
        for (int w = 0; w < NTHREADS / 32; w++) s += sred[w];
        atomicAdd(out, s * NPIX_INV);
    }
}

__global__ void zero_kernel(float* o, int n) {
    int i = blockIdx.x * blockDim.x + threadIdx.x;
    if (i < n) o[i] = 0.f;
}

extern "C" void kernel_launch(void* const* d_in, const int* in_sizes, int n_in,
                              void* d_out, int out_size)
{
    const float* img1 = (const float*)d_in[0];
    const float* img2 = (const float*)d_in[1];
    const float* kern = (const float*)d_in[2];
    float* out = (float*)d_out;

    zero_kernel<<<(out_size + 127) / 128, 128>>>(out, out_size);

    dim3 grid(IH / OUT_H, NIMG);   // 64 strips x 16 images = 1024 blocks
    ssim_kernel<<<grid, NTHREADS>>>(img1, img2, kern, out);
}